// round 5
// baseline (speedup 1.0000x reference)
#include <cuda_runtime.h>
#include <math.h>

// ESN: B=256, T=512, D=64, N=512, leak=0.5
// Output: [ X (B,T,N) fp32 ][ X_last (B,N) fp32 ]

#define BB 256
#define TT 512
#define DD 64
#define NN 512
#define LEAK 0.5f
#define NCTA 128
#define XR 34          // Xs row stride (words)

typedef unsigned long long ull;

__device__ unsigned g_flag[NCTA * 32];   // 128B-spaced flags, flag[i] = last step CTA i published

__device__ __forceinline__ void fma2(ull &acc, ull a, ull b) {
    asm("fma.rn.f32x2 %0, %1, %2, %0;" : "+l"(acc) : "l"(a), "l"(b));
}
__device__ __forceinline__ float2 unpack2(ull v) {
    float2 r; asm("mov.b64 {%0, %1}, %2;" : "=f"(r.x), "=f"(r.y) : "l"(v)); return r;
}
__device__ __forceinline__ void st_rel(unsigned* p, unsigned v) {
    asm volatile("st.release.gpu.global.u32 [%0], %1;" :: "l"(p), "r"(v) : "memory");
}
__device__ __forceinline__ unsigned ld_acq(const unsigned* p) {
    unsigned r;
    asm volatile("ld.acquire.gpu.global.u32 %0, [%1];" : "=r"(r) : "l"(p) : "memory");
    return r;
}

// ---------------------------------------------------------------------------
// Projection: U = inputs@W_in + b_in; x0 = leak*tanh(U0) at t=0.
// Block (0,0) also resets the flags (persist runs after, stream-ordered).
// ---------------------------------------------------------------------------
__global__ __launch_bounds__(128) void proj_kernel(
    const float* __restrict__ inp, const float* __restrict__ Win,
    const float* __restrict__ bin, float* __restrict__ X)
{
    __shared__ __align__(16) float As[DD][36];
    __shared__ __align__(16) float Wd[DD][64];

    const int tid = threadIdx.x;
    const int m0 = blockIdx.x * 32;
    const int n0 = blockIdx.y * 32;

    if (blockIdx.x == 0 && blockIdx.y == 0)
        g_flag[tid * 32] = 0u;          // tid 0..127 -> all 128 flags

    {
        int c = tid & 63, mi = tid >> 6;
        #pragma unroll
        for (int j = 0; j < 16; j++) {
            int m = j * 2 + mi;
            As[c][m] = inp[(m0 + m) * DD + c];
        }
    }
    {
        int n = tid & 31, kw = tid >> 5;
        #pragma unroll
        for (int j = 0; j < 16; j++) {
            int k = j * 4 + kw;
            float w = Win[k * NN + n0 + n];
            Wd[k][2 * n] = w; Wd[k][2 * n + 1] = w;
        }
    }
    __syncthreads();

    const int tx = tid & 7;
    const int ty = tid >> 3;
    ull acc0 = 0, acc1 = 0, acc2 = 0, acc3 = 0;

    #pragma unroll
    for (int k = 0; k < DD; k++) {
        ull a = *(const ull*)&As[k][2 * ty];
        const ulonglong2* bp = (const ulonglong2*)&Wd[k][8 * tx];
        ulonglong2 b01 = bp[0], b23 = bp[1];
        fma2(acc0, a, b01.x); fma2(acc1, a, b01.y);
        fma2(acc2, a, b23.x); fma2(acc3, a, b23.y);
    }

    const int r0 = m0 + 2 * ty;
    const int t0 = r0 & (TT - 1);
    const int nb = n0 + 4 * tx;
    ull accs[4] = {acc0, acc1, acc2, acc3};
    #pragma unroll
    for (int c = 0; c < 4; c++) {
        float2 v = unpack2(accs[c]);
        int n = nb + c;
        float b = bin[n];
        float u0 = v.x + b;
        float u1 = v.y + b;
        X[(size_t)r0 * NN + n]       = (t0 == 0) ? (LEAK * tanhf(u0)) : u0;
        X[(size_t)(r0 + 1) * NN + n] = u1;
    }
}

// ---------------------------------------------------------------------------
// Persistent recurrence: 128 CTAs = 8 m-slabs x 16 n-tiles, 256 threads.
// Dataflow (no group barrier): per-producer flags; consumer pipelines 16
// k-chunks (32 k each): wait flag -> LDG -> STS -> sync -> GEMM, prefetched.
// Xs[k][XR] plain transposed x_prev; Wd[k][64] dup pairs (built once).
// Per k per thread: LDS.64 (x_m,x_m1) + LDS.128 (wdup n, n+1) + 2 FFMA2.
// ---------------------------------------------------------------------------
__global__ __launch_bounds__(256, 1) void esn_persist(
    float* __restrict__ X, const float* __restrict__ Wres,
    const float* __restrict__ bres, float* __restrict__ xlast)
{
    extern __shared__ __align__(16) float smem[];
    float* Xs = smem;                 // [512][XR]
    float* Wd = smem + NN * XR;       // [512][64]

    const int tid = threadIdx.x;
    const int bx  = blockIdx.x;
    const int grp = bx & 7;
    const int nt  = bx >> 3;
    const int m0  = grp * 32;
    const int n0  = nt * 32;
    const int TN  = TT * NN;

    // Build duplicated W slab once: Wd[k][2n],[2n+1] = Wres[k][n0+n]
    {
        const int n = tid & 31;
        for (int k = tid >> 5; k < NN; k += 8) {
            float w = Wres[k * NN + n0 + n];
            *(float2*)&Wd[k * 64 + 2 * n] = make_float2(w, w);
        }
    }

    // GEMM mapping: 8 warps = 2 row-halves x 4 col-groups; thread: 2 rows x 2 cols
    const int w  = tid >> 5, l = tid & 31;
    const int wm = w & 1, wn = w >> 1;
    const int q  = l >> 2, c = l & 3;
    const int mloc = 16 * wm + 2 * q;        // local rows mloc, mloc+1
    const int nloc = 8 * wn + 2 * c;         // local cols nloc, nloc+1

    // staging mapping: r = row 0..31, g = float4 index 0..7
    const int r = tid >> 3;
    const int g = tid & 7;

    const float2 br2 = *(const float2*)&bres[n0 + nloc];
    const int r0 = m0 + mloc;

    // Prologue: stage own chunk of x_0; load prev-x registers from x_0
    {
        const float4 v = *(const float4*)&X[(size_t)(m0 + r) * TN + 32 * nt + 4 * g];
        float* d = Xs + (size_t)(32 * nt + 4 * g) * XR + r;
        d[0] = v.x; d[XR] = v.y; d[2 * XR] = v.z; d[3 * XR] = v.w;
    }
    float2 p0, p1;   // x_{t-1} at (r0, n0+nloc..+1), (r0+1, ...)
    p0 = *(const float2*)&X[(size_t)r0 * TN + n0 + nloc];
    p1 = *(const float2*)&X[(size_t)(r0 + 1) * TN + n0 + nloc];
    __syncthreads();

#define GEMM_CHUNK(J) { \
    _Pragma("unroll") \
    for (int kk = 0; kk < 32; kk++) { \
        int k = 32 * (J) + kk; \
        ull a = *(const ull*)&Xs[(size_t)k * XR + mloc]; \
        ulonglong2 b = *(const ulonglong2*)&Wd[(size_t)k * 64 + 2 * nloc]; \
        fma2(accA, a, b.x); fma2(accB, a, b.y); \
    } }

    for (int t = 1; t < TT; t++) {
        // Prefetch epilogue U operands (DRAM-latency, hidden under GEMM)
        size_t base = (size_t)r0 * TN + (size_t)t * NN + n0 + nloc;
        float2 u0 = __ldcg((const float2*)&X[base]);
        float2 u1 = __ldcg((const float2*)&X[base + TN]);

        ull accA = 0, accB = 0;   // accA: col nloc rows (m,m+1); accB: col nloc+1

        // Kick off prefetch of first remote chunk
        const size_t srow = (size_t)(m0 + r) * TN + (size_t)(t - 1) * NN;
        int j1 = (nt + 1) & 15;
        {
            unsigned* fl = &g_flag[(grp * 16 + j1) * 32];
            while (ld_acq(fl) < (unsigned)(t - 1)) { }
        }
        float4 v = __ldcg((const float4*)&X[srow + 32 * j1 + 4 * g]);

        // GEMM own chunk (already in smem from previous epilogue)
        GEMM_CHUNK(nt);

        // Pipeline remaining 15 chunks
        #pragma unroll 1
        for (int jj = 1; jj < 16; jj++) {
            int j = (nt + jj) & 15;
            // store current prefetched chunk
            float* d = Xs + (size_t)(32 * j + 4 * g) * XR + r;
            d[0] = v.x; d[XR] = v.y; d[2 * XR] = v.z; d[3 * XR] = v.w;
            if (jj < 15) {
                int jn = (nt + jj + 1) & 15;
                unsigned* fl = &g_flag[(grp * 16 + jn) * 32];
                while (ld_acq(fl) < (unsigned)(t - 1)) { }
                v = __ldcg((const float4*)&X[srow + 32 * jn + 4 * g]);
            }
            __syncthreads();
            GEMM_CHUNK(j);
        }

        // Epilogue: x_t = 0.5*x_prev + 0.5*tanh(U + s + b_res)
        float2 sA = unpack2(accA), sB = unpack2(accB);
        float2 o0, o1;
        o0.x = 0.5f * p0.x + 0.5f * tanhf(u0.x + sA.x + br2.x);
        o0.y = 0.5f * p0.y + 0.5f * tanhf(u0.y + sB.x + br2.y);
        o1.x = 0.5f * p1.x + 0.5f * tanhf(u1.x + sA.y + br2.x);
        o1.y = 0.5f * p1.y + 0.5f * tanhf(u1.y + sB.y + br2.y);
        p0 = o0; p1 = o1;

        // Publish to global
        *(float2*)&X[base]      = o0;
        *(float2*)&X[base + TN] = o1;
        if (t == TT - 1) {
            *(float2*)&xlast[(size_t)r0 * NN + n0 + nloc]       = o0;
            *(float2*)&xlast[(size_t)(r0 + 1) * NN + n0 + nloc] = o1;
        }

        // Stash own chunk into smem for next step's GEMM-own:
        // Xs[k=n0+nloc][mloc..+1] = (o0.x, o1.x); next col = (o0.y, o1.y)
        *(float2*)&Xs[(size_t)(n0 + nloc) * XR + mloc]     = make_float2(o0.x, o1.x);
        *(float2*)&Xs[(size_t)(n0 + nloc + 1) * XR + mloc] = make_float2(o0.y, o1.y);

        // Release: own tile visible, then raise flag; sync so all threads'
        // stores (global + smem own-chunk) are done before next iteration.
        __syncthreads();
        if (tid == 0 && t < TT - 1)
            st_rel(&g_flag[(grp * 16 + nt) * 32], (unsigned)t);
    }
#undef GEMM_CHUNK
}

extern "C" void kernel_launch(void* const* d_in, const int* in_sizes, int n_in,
                              void* d_out, int out_size)
{
    const float* inp  = (const float*)d_in[0];
    const float* Win  = (const float*)d_in[1];
    const float* bin  = (const float*)d_in[2];
    const float* Wres = (const float*)d_in[3];
    const float* bres = (const float*)d_in[4];

    float* X = (float*)d_out;                       // (B, T, N)
    float* xlast = X + (size_t)BB * TT * NN;        // (B, N)

    const int smem_bytes = (NN * XR + NN * 64) * sizeof(float);  // 200704
    cudaFuncSetAttribute(esn_persist, cudaFuncAttributeMaxDynamicSharedMemorySize, smem_bytes);

    dim3 g1(BB * TT / 32, NN / 32);
    proj_kernel<<<g1, 128>>>(inp, Win, bin, X);

    esn_persist<<<NCTA, 256, smem_bytes>>>(X, Wres, bres, xlast);
}

// round 6
// speedup vs baseline: 2.7093x; 2.7093x over previous
#include <cuda_runtime.h>
#include <math.h>

// ESN: B=256, T=512, D=64, N=512, leak=0.5
// Output: [ X (B,T,N) fp32 ][ X_last (B,N) fp32 ]

#define BB 256
#define TT 512
#define DD 64
#define NN 512
#define LEAK 0.5f
#define NCTA 128
#define AS 516         // smem row stride (words) for A / W slabs: (4m+k)%32 distinct
#define NGRP 8
#define GRP_SZ 16

typedef unsigned long long ull;

__device__ unsigned g_cnt[NGRP * 32];   // 128B-spaced group counters

__device__ __forceinline__ void fma2(ull &acc, ull a, ull b) {
    asm("fma.rn.f32x2 %0, %1, %2, %0;" : "+l"(acc) : "l"(a), "l"(b));
}
__device__ __forceinline__ float2 unpack2(ull v) {
    float2 r; asm("mov.b64 {%0, %1}, %2;" : "=f"(r.x), "=f"(r.y) : "l"(v)); return r;
}
__device__ __forceinline__ unsigned atom_add_rel(unsigned* p, unsigned v) {
    unsigned r;
    asm volatile("atom.add.release.gpu.global.u32 %0, [%1], %2;"
                 : "=r"(r) : "l"(p), "r"(v) : "memory");
    return r;
}
__device__ __forceinline__ unsigned ld_acq(const unsigned* p) {
    unsigned r;
    asm volatile("ld.acquire.gpu.global.u32 %0, [%1];" : "=r"(r) : "l"(p) : "memory");
    return r;
}
__device__ __forceinline__ float tf32r(float x) {
    unsigned u; asm("cvt.rna.tf32.f32 %0, %1;" : "=r"(u) : "f"(x));
    return __uint_as_float(u);
}
// D(16x8) += A(16x8,tf32) * B(8x8,tf32); standard m16n8k8 fragment layout.
__device__ __forceinline__ void mma8(float &c0, float &c1, float &c2, float &c3,
                                     float a0, float a1, float a2, float a3,
                                     float b0, float b1) {
    asm("mma.sync.aligned.m16n8k8.row.col.f32.tf32.tf32.f32 "
        "{%0,%1,%2,%3},{%4,%5,%6,%7},{%8,%9},{%0,%1,%2,%3};"
        : "+f"(c0), "+f"(c1), "+f"(c2), "+f"(c3)
        : "r"(__float_as_uint(a0)), "r"(__float_as_uint(a1)),
          "r"(__float_as_uint(a2)), "r"(__float_as_uint(a3)),
          "r"(__float_as_uint(b0)), "r"(__float_as_uint(b1)));
}

// ---------------------------------------------------------------------------
// Projection: U = inputs@W_in + b_in; x0 = leak*tanh(U0) at t=0.
// Block (0,0) also resets the group counters.
// ---------------------------------------------------------------------------
__global__ __launch_bounds__(128) void proj_kernel(
    const float* __restrict__ inp, const float* __restrict__ Win,
    const float* __restrict__ bin, float* __restrict__ X)
{
    __shared__ __align__(16) float Ash[DD][36];
    __shared__ __align__(16) float Wd[DD][64];

    const int tid = threadIdx.x;
    const int m0 = blockIdx.x * 32;
    const int n0 = blockIdx.y * 32;

    if (blockIdx.x == 0 && blockIdx.y == 0 && tid < NGRP)
        g_cnt[tid * 32] = 0u;

    {
        int c = tid & 63, mi = tid >> 6;
        #pragma unroll
        for (int j = 0; j < 16; j++) {
            int m = j * 2 + mi;
            Ash[c][m] = inp[(m0 + m) * DD + c];
        }
    }
    {
        int n = tid & 31, kw = tid >> 5;
        #pragma unroll
        for (int j = 0; j < 16; j++) {
            int k = j * 4 + kw;
            float w = Win[k * NN + n0 + n];
            Wd[k][2 * n] = w; Wd[k][2 * n + 1] = w;
        }
    }
    __syncthreads();

    const int tx = tid & 7;
    const int ty = tid >> 3;
    ull acc0 = 0, acc1 = 0, acc2 = 0, acc3 = 0;

    #pragma unroll
    for (int k = 0; k < DD; k++) {
        ull a = *(const ull*)&Ash[k][2 * ty];
        const ulonglong2* bp = (const ulonglong2*)&Wd[k][8 * tx];
        ulonglong2 b01 = bp[0], b23 = bp[1];
        fma2(acc0, a, b01.x); fma2(acc1, a, b01.y);
        fma2(acc2, a, b23.x); fma2(acc3, a, b23.y);
    }

    const int r0 = m0 + 2 * ty;
    const int t0 = r0 & (TT - 1);
    const int nb = n0 + 4 * tx;
    ull accs[4] = {acc0, acc1, acc2, acc3};
    #pragma unroll
    for (int c = 0; c < 4; c++) {
        float2 v = unpack2(accs[c]);
        int n = nb + c;
        float b = bin[n];
        float u0 = v.x + b;
        float u1 = v.y + b;
        X[(size_t)r0 * NN + n]       = (t0 == 0) ? (LEAK * tanhf(u0)) : u0;
        X[(size_t)(r0 + 1) * NN + n] = u1;
    }
}

// ---------------------------------------------------------------------------
// Persistent tensor-core recurrence: 128 CTAs = 8 m-slabs x 16 n-tiles,
// 128 threads = 4 warps (2m x 2n of m16n16). Per step:
//   stage A = tf32(x_prev slab 32x512) -> smem;  U prefetch;
//   GEMM: 64 k8-chunks x (A-frag LDS + W_hi/W_lo B-frags + 4 HMMA);
//   epilogue fp32: x_t = 0.5*x_prev(reg) + 0.5*tanh(U + sH+sL + b_res);
//   STG; 16-CTA group barrier.
// W_hi/W_lo tf32 split staged once (W exact to ~22 bits).
// ---------------------------------------------------------------------------
__global__ __launch_bounds__(128, 1) void esn_mma(
    float* __restrict__ X, const float* __restrict__ Wres,
    const float* __restrict__ bres, float* __restrict__ xlast)
{
    extern __shared__ __align__(16) float smem[];
    float* Asm = smem;              // [32][AS]  tf32(x_prev), row-major m x k
    float* Wh  = smem + 32 * AS;    // [32][AS]  tf32 hi, n-major: Wh[n][k]
    float* Wl  = Wh  + 32 * AS;     // [32][AS]  tf32 lo

    const int tid  = threadIdx.x;
    const int warp = tid >> 5, lane = tid & 31;
    const int bx   = blockIdx.x;
    const int grp  = bx & 7;
    const int m0   = grp * 32;
    const int n0   = (bx >> 3) * 32;
    const int TN   = TT * NN;
    unsigned* cnt  = &g_cnt[grp * 32];

    // ---- stage W hi/lo once ----
    {
        const int n = tid & 31;
        for (int k = tid >> 5; k < NN; k += 4) {
            float w  = Wres[k * NN + n0 + n];
            float hi = tf32r(w);
            Wh[n * AS + k] = hi;
            Wl[n * AS + k] = tf32r(w - hi);
        }
    }

    // fragment mapping
    const int wm  = warp & 1, wn = warp >> 1;
    const int gid = lane >> 2, tig = lane & 3;
    const int r0  = m0 + 16 * wm + gid;          // rows r0, r0+8
    const int cb  = n0 + 16 * wn + 2 * tig;      // cols cb,cb+1 (n8=0); +8 (n8=1)

    const float* arow0 = Asm + (16 * wm + gid) * AS;
    const float* arow1 = arow0 + 8 * AS;
    const float* wh0 = Wh + (16 * wn + gid) * AS;
    const float* wh1 = wh0 + 8 * AS;
    const float* wl0 = Wl + (16 * wn + gid) * AS;
    const float* wl1 = wl0 + 8 * AS;

    const float2 br0 = *(const float2*)&bres[cb];
    const float2 br1 = *(const float2*)&bres[cb + 8];

    // register-carried x_prev at this thread's output positions (from x0)
    float2 p00 = *(const float2*)&X[(size_t)r0 * TN + cb];
    float2 p01 = *(const float2*)&X[(size_t)r0 * TN + cb + 8];
    float2 p10 = *(const float2*)&X[(size_t)(r0 + 8) * TN + cb];
    float2 p11 = *(const float2*)&X[(size_t)(r0 + 8) * TN + cb + 8];

    for (int t = 1; t < TT; t++) {
        // ---- stage A slab: 32 rows x 512 k of tf32(x_{t-1}) ----
        {
            const float* src = X + (size_t)m0 * TN + (size_t)(t - 1) * NN;
            #pragma unroll
            for (int g = 0; g < 8; g++) {
                int r = warp + 4 * g;
                const float4* rp = (const float4*)(src + (size_t)r * TN);
                float* dr = Asm + r * AS;
                #pragma unroll
                for (int q = 0; q < 4; q++) {
                    int i4 = lane + 32 * q;
                    float4 v = __ldcg(rp + i4);
                    *(float4*)(dr + 4 * i4) = make_float4(
                        tf32r(v.x), tf32r(v.y), tf32r(v.z), tf32r(v.w));
                }
            }
        }

        // ---- prefetch U (this step's preactivation, written by proj) ----
        size_t base = (size_t)r0 * TN + (size_t)t * NN + cb;
        float2 u00 = __ldcg((const float2*)&X[base]);
        float2 u01 = __ldcg((const float2*)&X[base + 8]);
        float2 u10 = __ldcg((const float2*)&X[base + (size_t)8 * TN]);
        float2 u11 = __ldcg((const float2*)&X[base + (size_t)8 * TN + 8]);

        __syncthreads();

        // ---- tensor GEMM: 4 independent acc chains (n8 x {hi,lo}) ----
        float h00 = 0.f, h01 = 0.f, h02 = 0.f, h03 = 0.f;   // n8=0 hi
        float h10 = 0.f, h11 = 0.f, h12 = 0.f, h13 = 0.f;   // n8=1 hi
        float l00 = 0.f, l01 = 0.f, l02 = 0.f, l03 = 0.f;   // n8=0 lo
        float l10 = 0.f, l11 = 0.f, l12 = 0.f, l13 = 0.f;   // n8=1 lo

        #pragma unroll 4
        for (int kb = 0; kb < NN; kb += 8) {
            float a0 = arow0[kb + tig];
            float a1 = arow1[kb + tig];
            float a2 = arow0[kb + tig + 4];
            float a3 = arow1[kb + tig + 4];
            mma8(h00, h01, h02, h03, a0, a1, a2, a3, wh0[kb + tig], wh0[kb + tig + 4]);
            mma8(h10, h11, h12, h13, a0, a1, a2, a3, wh1[kb + tig], wh1[kb + tig + 4]);
            mma8(l00, l01, l02, l03, a0, a1, a2, a3, wl0[kb + tig], wl0[kb + tig + 4]);
            mma8(l10, l11, l12, l13, a0, a1, a2, a3, wl1[kb + tig], wl1[kb + tig + 4]);
        }

        // ---- epilogue (fp32): x_t = 0.5*x_prev + 0.5*tanh(U + s + b_res) ----
        float2 o00, o01, o10, o11;
        o00.x = 0.5f * p00.x + 0.5f * tanhf(u00.x + (h00 + l00) + br0.x);
        o00.y = 0.5f * p00.y + 0.5f * tanhf(u00.y + (h01 + l01) + br0.y);
        o10.x = 0.5f * p10.x + 0.5f * tanhf(u10.x + (h02 + l02) + br0.x);
        o10.y = 0.5f * p10.y + 0.5f * tanhf(u10.y + (h03 + l03) + br0.y);
        o01.x = 0.5f * p01.x + 0.5f * tanhf(u01.x + (h10 + l10) + br1.x);
        o01.y = 0.5f * p01.y + 0.5f * tanhf(u01.y + (h11 + l11) + br1.y);
        o11.x = 0.5f * p11.x + 0.5f * tanhf(u11.x + (h12 + l12) + br1.x);
        o11.y = 0.5f * p11.y + 0.5f * tanhf(u11.y + (h13 + l13) + br1.y);
        p00 = o00; p01 = o01; p10 = o10; p11 = o11;

        *(float2*)&X[base]                      = o00;
        *(float2*)&X[base + 8]                  = o01;
        *(float2*)&X[base + (size_t)8 * TN]     = o10;
        *(float2*)&X[base + (size_t)8 * TN + 8] = o11;
        if (t == TT - 1) {
            *(float2*)&xlast[(size_t)r0 * NN + cb]           = o00;
            *(float2*)&xlast[(size_t)r0 * NN + cb + 8]       = o01;
            *(float2*)&xlast[(size_t)(r0 + 8) * NN + cb]     = o10;
            *(float2*)&xlast[(size_t)(r0 + 8) * NN + cb + 8] = o11;
        }

        // ---- 16-CTA group barrier ----
        if (t < TT - 1) {
            __syncthreads();
            if (tid == 0) {
                atom_add_rel(cnt, 1u);
                unsigned target = (unsigned)t * GRP_SZ;
                while (ld_acq(cnt) < target) { }
            }
            __syncthreads();
        }
    }
}

extern "C" void kernel_launch(void* const* d_in, const int* in_sizes, int n_in,
                              void* d_out, int out_size)
{
    const float* inp  = (const float*)d_in[0];
    const float* Win  = (const float*)d_in[1];
    const float* bin  = (const float*)d_in[2];
    const float* Wres = (const float*)d_in[3];
    const float* bres = (const float*)d_in[4];

    float* X = (float*)d_out;                       // (B, T, N)
    float* xlast = X + (size_t)BB * TT * NN;        // (B, N)

    const int smem_bytes = 3 * 32 * AS * sizeof(float);   // 198144
    cudaFuncSetAttribute(esn_mma, cudaFuncAttributeMaxDynamicSharedMemorySize, smem_bytes);

    dim3 g1(BB * TT / 32, NN / 32);
    proj_kernel<<<g1, 128>>>(inp, Win, bin, X);

    esn_mma<<<NCTA, 128, smem_bytes>>>(X, Wres, bres, xlast);
}